// round 4
// baseline (speedup 1.0000x reference)
#include <cuda_runtime.h>
#include <math.h>

#define N_TOK 8192
#define DIM   4096
#define NEXP  16
#define TPB   256
#define NWARP 8
#define TOK   64                 /* tokens per block */
#define KSPLIT 4                 /* k-split across blocks */
#define KBLK  (DIM / KSPLIT)     /* 1024 k per block */
#define KSL   (KBLK / NWARP)     /* 128 k per warp */
#define XTILE 16                 /* k per x tile */
#define NT    (KSL / XTILE)      /* 8 tiles */
#define GCH   32                 /* gate chunk rows (= 2 tiles) */

#define SM_GS (NWARP * GCH * NEXP * 2)   /* duplicated gate: 8192 f */
#define SM_XS (NWARP * XTILE * TOK)      /* 8192 f */
#define SM_LG (TOK * NEXP)               /* 1024 f */
#define SM_FLOATS (SM_GS + SM_XS + SM_LG)
#define SM_BYTES  (SM_FLOATS * 4)        /* 69632 B -> 3 CTAs/SM */

__device__ float g_part[KSPLIT][N_TOK][NEXP];   /* 2MB scratch */

#define FMA2(acc, a, b) \
    asm("fma.rn.f32x2 %0, %1, %2, %0;" : "+l"(acc) : "l"(a), "l"(b))

__global__ void __launch_bounds__(TPB, 3)
router_k1(const float* __restrict__ x, const float* __restrict__ gate)
{
    extern __shared__ float sm[];
    float* gs = sm;                  // [NWARP][GCH][32]  gate, each value duplicated
    float* xs = gs + SM_GS;          // [NWARP][XTILE][TOK] transposed x tile
    float* lg = xs + SM_XS;          // [TOK][16] block logits (atomic accum)

    const int tid = threadIdx.x;
    const int w = tid >> 5, l = tid & 31;
    const int s = blockIdx.x >> 7;                 // k-split id 0..3
    const int tokBase = (blockIdx.x & 127) * TOK;
    const int kb = s * KBLK + w * KSL;             // warp k start

    if (tid < (TOK * NEXP) / 4)
        ((float4*)lg)[tid] = make_float4(0.f, 0.f, 0.f, 0.f);
    __syncthreads();

    float* gs_w = gs + w * (GCH * 32);
    float* xs_w = xs + w * (XTILE * TOK);

    const int cq = l & 3;        // load: col quad (k)
    const int g8 = l >> 2;       // load: token group 0..7
    const int tq = l & 15;       // compute: token quad -> tokens 4tq..4tq+3
    const int eh = l >> 4;       // compute: expert half -> experts 8eh..8eh+7

    // acc[e]: f32x2 over token pair; A = tokens {4tq,4tq+1}, B = {4tq+2,4tq+3}
    unsigned long long accA[8], accB[8];
#pragma unroll
    for (int i = 0; i < 8; i++) { accA[i] = 0ull; accB[i] = 0ull; }

    float vbuf[2][4][4];   // [pass p][row d][component j]

    // prologue: x tile 0 -> regs (rows 32p+4*g8+d, cols 4cq..4cq+3)
    {
        const float* xb = x + (size_t)tokBase * DIM + kb + 4 * cq;
#pragma unroll
        for (int p = 0; p < 2; p++)
#pragma unroll
            for (int d = 0; d < 4; d++) {
                float4 v = *(const float4*)(xb + (size_t)(p * 32 + 4 * g8 + d) * DIM);
                vbuf[p][d][0] = v.x; vbuf[p][d][1] = v.y;
                vbuf[p][d][2] = v.z; vbuf[p][d][3] = v.w;
            }
    }

    for (int t = 0; t < NT; t++) {
        __syncwarp();   // prior compute's xs reads complete

        // STS current tile, transposed in registers -> [k][tok], STS.128
#pragma unroll
        for (int p = 0; p < 2; p++)
#pragma unroll
            for (int j = 0; j < 4; j++) {
                float4 sv = make_float4(vbuf[p][0][j], vbuf[p][1][j],
                                        vbuf[p][2][j], vbuf[p][3][j]);
                *(float4*)(xs_w + (4 * cq + j) * TOK + (p * 32 + 4 * g8)) = sv;
            }

        // restage duplicated gate every 2 tiles (GCH = 2*XTILE)
        if ((t & 1) == 0) {
            const float* gsrc = gate + (size_t)(kb + (t >> 1) * GCH) * NEXP;
#pragma unroll
            for (int p = 0; p < 4; p++) {
                float4 v = ((const float4*)gsrc)[p * 32 + l];
                float* d0 = gs_w + (size_t)(p * 32 + l) * 8;
                *(float4*)d0       = make_float4(v.x, v.x, v.y, v.y);
                *(float4*)(d0 + 4) = make_float4(v.z, v.z, v.w, v.w);
            }
        }

        // prefetch next x tile into regs (overlaps compute below)
        if (t + 1 < NT) {
            const float* xb = x + (size_t)tokBase * DIM + kb + (t + 1) * XTILE + 4 * cq;
#pragma unroll
            for (int p = 0; p < 2; p++)
#pragma unroll
                for (int d = 0; d < 4; d++) {
                    float4 v = *(const float4*)(xb + (size_t)(p * 32 + 4 * g8 + d) * DIM);
                    vbuf[p][d][0] = v.x; vbuf[p][d][1] = v.y;
                    vbuf[p][d][2] = v.z; vbuf[p][d][3] = v.w;
                }
        }
        __syncwarp();

        const int gofs = (t & 1) * XTILE;
#pragma unroll
        for (int kk = 0; kk < XTILE; kk++) {
            ulonglong2 xv = *(const ulonglong2*)(xs_w + kk * TOK + 4 * tq);
            const ulonglong2* grow =
                (const ulonglong2*)(gs_w + (gofs + kk) * 32 + eh * 16);
            ulonglong2 G0 = grow[0], G1 = grow[1], G2 = grow[2], G3 = grow[3];
            FMA2(accA[0], xv.x, G0.x); FMA2(accA[1], xv.x, G0.y);
            FMA2(accA[2], xv.x, G1.x); FMA2(accA[3], xv.x, G1.y);
            FMA2(accA[4], xv.x, G2.x); FMA2(accA[5], xv.x, G2.y);
            FMA2(accA[6], xv.x, G3.x); FMA2(accA[7], xv.x, G3.y);
            FMA2(accB[0], xv.y, G0.x); FMA2(accB[1], xv.y, G0.y);
            FMA2(accB[2], xv.y, G1.x); FMA2(accB[3], xv.y, G1.y);
            FMA2(accB[4], xv.y, G2.x); FMA2(accB[5], xv.y, G2.y);
            FMA2(accB[6], xv.y, G3.x); FMA2(accB[7], xv.y, G3.y);
        }
    }

    // reduce across warps: one-shot smem atomics (spread addresses)
#pragma unroll
    for (int e = 0; e < 8; e++) {
        float2 a = *(float2*)&accA[e];
        float2 b = *(float2*)&accB[e];
        float* base = lg + (4 * tq) * NEXP + 8 * eh + e;
        atomicAdd(base + 0 * NEXP, a.x);
        atomicAdd(base + 1 * NEXP, a.y);
        atomicAdd(base + 2 * NEXP, b.x);
        atomicAdd(base + 3 * NEXP, b.y);
    }
    __syncthreads();

    // write block partials to scratch
    {
        int tok = tid >> 2, q = tid & 3;
        *(float4*)&g_part[s][tokBase + tok][q * 4] =
            *(const float4*)(lg + tok * NEXP + q * 4);
    }
}

__global__ void __launch_bounds__(128)
router_k2(float* __restrict__ out, int out_size)
{
    const int tok = blockIdx.x * 128 + threadIdx.x;
    float v[NEXP];
#pragma unroll
    for (int q = 0; q < 4; q++) {
        float4 a = *(const float4*)&g_part[0][tok][q * 4];
#pragma unroll
        for (int sp = 1; sp < KSPLIT; sp++) {
            float4 b = *(const float4*)&g_part[sp][tok][q * 4];
            a.x += b.x; a.y += b.y; a.z += b.z; a.w += b.w;
        }
        v[q * 4 + 0] = a.x; v[q * 4 + 1] = a.y;
        v[q * 4 + 2] = a.z; v[q * 4 + 3] = a.w;
    }

    float v1 = -INFINITY, v2 = -INFINITY;
    int   i1 = -1,        i2 = -1;
#pragma unroll
    for (int e = 0; e < NEXP; e++) {
        float tv = v[e];
        if (tv > v1)      { v2 = v1; i2 = i1; v1 = tv; i1 = e; }
        else if (tv > v2) { v2 = tv; i2 = e; }
    }

#pragma unroll
    for (int e = 0; e < NEXP; e++) {
        float sc = (e == i1 || e == i2) ? (1.0f / (1.0f + expf(-v[e]))) : 0.0f;
        out[(size_t)e * N_TOK + tok] = sc;    // lanes = consecutive tokens: coalesced
    }

    if (out_size >= 2 * NEXP * N_TOK) {
        float fv = (float)tok;
#pragma unroll
        for (int e = 0; e < NEXP; e++)
            out[(size_t)NEXP * N_TOK + (size_t)e * N_TOK + tok] = fv;
    }
}

extern "C" void kernel_launch(void* const* d_in, const int* in_sizes, int n_in,
                              void* d_out, int out_size)
{
    const float* x    = (const float*)d_in[0];
    const float* gate = (const float*)d_in[1];
    float* out = (float*)d_out;

    cudaFuncSetAttribute(router_k1,
                         cudaFuncAttributeMaxDynamicSharedMemorySize, SM_BYTES);

    router_k1<<<KSPLIT * (N_TOK / TOK), TPB, SM_BYTES>>>(x, gate);  // 512 blocks
    router_k2<<<N_TOK / 128, 128>>>(out, out_size);
}

// round 5
// speedup vs baseline: 2.0446x; 2.0446x over previous
#include <cuda_runtime.h>
#include <math.h>

#define N_TOK 8192
#define DIM   4096
#define NEXP  16
#define TPB   256
#define NWARP 8
#define TOK   32                  /* tokens per block */
#define KSL   (DIM / NWARP)       /* 512 k per warp */
#define XTILE 32                  /* k per pipeline stage */
#define NT    (KSL / XTILE)       /* 16 tiles */
#define GSTR  36                  /* dup-gate row stride (floats, 16B-aligned) */

#define SM_GS   (NWARP * XTILE * GSTR)    /*  9216 f : dup gate tiles */
#define SM_XS   (NWARP * XTILE * TOK)     /*  8192 f : swizzled x tiles */
#define SM_PART (NWARP * TOK * NEXP)      /*  4096 f : per-warp partials */
#define SM_LG   (TOK * NEXP)              /*   512 f : block logits */
#define SM_FLOATS (SM_GS + SM_XS + SM_PART + SM_LG)
#define SM_BYTES  (SM_FLOATS * 4)         /* 88064 B -> 2 CTAs/SM */

#define FMA2(acc, a, b) \
    asm("fma.rn.f32x2 %0, %1, %2, %0;" : "+l"(acc) : "l"(a), "l"(b))

__global__ void __launch_bounds__(TPB, 2)
router_kernel(const float* __restrict__ x,
              const float* __restrict__ gate,
              float* __restrict__ out, int out_size)
{
    extern __shared__ float sm[];
    float* gs   = sm;                 // [NWARP][XTILE][GSTR] gate, duplicated {g,g}
    float* xs   = gs + SM_GS;         // [NWARP][XTILE][32]   x, [k][tok], XOR-swizzled
    float* part = xs + SM_XS;         // [NWARP][TOK][16]
    float* lg   = part + SM_PART;     // [TOK][16]

    const int tid = threadIdx.x;
    const int w = tid >> 5, l = tid & 31;
    const int tokBase = blockIdx.x * TOK;
    const int kb = w * KSL;

    float* gs_w = gs + w * (XTILE * GSTR);
    float* xs_w = xs + w * (XTILE * TOK);

    // ---- load-phase lane roles ----
    const int q  = l & 7;    // k quad within tile (k = 4q+j)
    const int r  = l >> 3;   // token sub-row 0..3 (token = r + 4d)
    // ---- gate-load lane roles ----
    const int i4 = l & 3;    // expert quad
    const int gr = l >> 2;   // gate row 0..7 (row = gr + 8d)
    // ---- compute lane roles ----
    const int tq = l & 7;    // token quad: tokens 4tq..4tq+3
    const int eq = l >> 3;   // expert quad: experts 4eq..4eq+3

    // acc0[e] = tokens {4tq, 4tq+1}, acc1[e] = {4tq+2, 4tq+3}, expert 4eq+e
    unsigned long long acc0[4], acc1[4];
#pragma unroll
    for (int i = 0; i < 4; i++) { acc0[i] = 0ull; acc1[i] = 0ull; }

    float4 xbuf[8];   // x tile prefetch: rows r+4d, cols 4q..4q+3
    float4 gbuf[4];   // gate tile prefetch: rows gr+8d, experts 4*i4..

    // ---- prologue: tile 0 into registers ----
    {
        const float* xb = x + (size_t)(tokBase + r) * DIM + kb + 4 * q;
#pragma unroll
        for (int d = 0; d < 8; d++)
            xbuf[d] = *(const float4*)(xb + (size_t)(4 * d) * DIM);
        const float* gb = gate + (size_t)(kb + gr) * NEXP + 4 * i4;
#pragma unroll
        for (int d = 0; d < 4; d++)
            gbuf[d] = *(const float4*)(gb + (size_t)(8 * d) * NEXP);
    }

    for (int t = 0; t < NT; t++) {
        __syncwarp();   // previous compute's smem reads complete

        // ---- STS x tile, transposed + XOR-swizzled: xs[kk][4*(t4^q)+ (tok&3)] ----
#pragma unroll
        for (int d = 0; d < 8; d++) {
            const float vv0 = xbuf[d].x, vv1 = xbuf[d].y,
                        vv2 = xbuf[d].z, vv3 = xbuf[d].w;
            float* base = xs_w + 4 * (d ^ q) + r;   // swizzle: physical quad = d^q
            base[(4 * q + 0) * TOK] = vv0;
            base[(4 * q + 1) * TOK] = vv1;
            base[(4 * q + 2) * TOK] = vv2;
            base[(4 * q + 3) * TOK] = vv3;
        }
        // ---- STS gate tile, duplicated {g,g} pairs ----
#pragma unroll
        for (int d = 0; d < 4; d++) {
            float4 g = gbuf[d];
            float* dst = gs_w + (gr + 8 * d) * GSTR + 8 * i4;
            *(float4*)dst       = make_float4(g.x, g.x, g.y, g.y);
            *(float4*)(dst + 4) = make_float4(g.z, g.z, g.w, g.w);
        }

        // ---- prefetch tile t+1 (overlaps compute below) ----
        if (t + 1 < NT) {
            const int kn = kb + (t + 1) * XTILE;
            const float* xb = x + (size_t)(tokBase + r) * DIM + kn + 4 * q;
#pragma unroll
            for (int d = 0; d < 8; d++)
                xbuf[d] = *(const float4*)(xb + (size_t)(4 * d) * DIM);
            const float* gb = gate + (size_t)(kn + gr) * NEXP + 4 * i4;
#pragma unroll
            for (int d = 0; d < 4; d++)
                gbuf[d] = *(const float4*)(gb + (size_t)(8 * d) * NEXP);
        }
        __syncwarp();

        // ---- compute 32 k steps ----
#pragma unroll
        for (int kk = 0; kk < XTILE; kk++) {
            ulonglong2 xv = *(const ulonglong2*)
                (xs_w + kk * TOK + 4 * (tq ^ ((kk >> 2) & 7)));
            const float* grow = gs_w + kk * GSTR + 8 * eq;
            ulonglong2 Ga = *(const ulonglong2*)grow;        // exp 4eq+0, 4eq+1
            ulonglong2 Gb = *(const ulonglong2*)(grow + 4);  // exp 4eq+2, 4eq+3
            FMA2(acc0[0], xv.x, Ga.x); FMA2(acc0[1], xv.x, Ga.y);
            FMA2(acc0[2], xv.x, Gb.x); FMA2(acc0[3], xv.x, Gb.y);
            FMA2(acc1[0], xv.y, Ga.x); FMA2(acc1[1], xv.y, Ga.y);
            FMA2(acc1[2], xv.y, Gb.x); FMA2(acc1[3], xv.y, Gb.y);
        }
    }

    // ---- per-warp partials: lane owns 4 tokens x 4 experts ----
#pragma unroll
    for (int j = 0; j < 4; j++) {
        int tok = 4 * tq + j;
        float4 pv;
        if (j == 0) pv = make_float4(((float2*)&acc0[0])->x, ((float2*)&acc0[1])->x,
                                     ((float2*)&acc0[2])->x, ((float2*)&acc0[3])->x);
        if (j == 1) pv = make_float4(((float2*)&acc0[0])->y, ((float2*)&acc0[1])->y,
                                     ((float2*)&acc0[2])->y, ((float2*)&acc0[3])->y);
        if (j == 2) pv = make_float4(((float2*)&acc1[0])->x, ((float2*)&acc1[1])->x,
                                     ((float2*)&acc1[2])->x, ((float2*)&acc1[3])->x);
        if (j == 3) pv = make_float4(((float2*)&acc1[0])->y, ((float2*)&acc1[1])->y,
                                     ((float2*)&acc1[2])->y, ((float2*)&acc1[3])->y);
        *(float4*)(part + (size_t)(w * TOK + tok) * NEXP + 4 * eq) = pv;
    }
    __syncthreads();

    // ---- reduce 8 warps: thread -> (token, 2 experts) ----
    {
        int tok = tid >> 3, e2 = (tid & 7) * 2;
        float2 s = make_float2(0.f, 0.f);
#pragma unroll
        for (int ww = 0; ww < NWARP; ww++) {
            float2 v = *(const float2*)(part + (size_t)(ww * TOK + tok) * NEXP + e2);
            s.x += v.x; s.y += v.y;
        }
        *(float2*)(lg + tok * NEXP + e2) = s;
    }
    __syncthreads();

    // ---- top-2 + sigmoid + transposed score writes ----
    if (tid < TOK) {
        int tok = tid;
        float v[NEXP];
#pragma unroll
        for (int e = 0; e < NEXP; e++) v[e] = lg[tok * NEXP + e];
        float v1 = -INFINITY, v2 = -INFINITY;
        int   i1 = -1,        i2 = -1;
#pragma unroll
        for (int e = 0; e < NEXP; e++) {
            float tv = v[e];
            if (tv > v1)      { v2 = v1; i2 = i1; v1 = tv; i1 = e; }
            else if (tv > v2) { v2 = tv; i2 = e; }
        }
        int gtok = tokBase + tok;
#pragma unroll
        for (int e = 0; e < NEXP; e++) {
            float sc = (e == i1 || e == i2) ? (1.0f / (1.0f + expf(-v[e]))) : 0.0f;
            out[(size_t)e * N_TOK + gtok] = sc;   // 32 consecutive tokens: coalesced
        }
    }

    // ---- token_indices (second output region), values as floats ----
    if (out_size >= 2 * NEXP * N_TOK) {
        int e  = tid >> 4;            // 0..15
        int c2 = (tid & 15) * 2;      // token pair within block
        int gtok = tokBase + c2;
        float2 fv = make_float2((float)gtok, (float)(gtok + 1));
        *(float2*)(out + (size_t)NEXP * N_TOK + (size_t)e * N_TOK + gtok) = fv;
    }
}

extern "C" void kernel_launch(void* const* d_in, const int* in_sizes, int n_in,
                              void* d_out, int out_size)
{
    const float* x    = (const float*)d_in[0];
    const float* gate = (const float*)d_in[1];
    float* out = (float*)d_out;

    cudaFuncSetAttribute(router_kernel,
                         cudaFuncAttributeMaxDynamicSharedMemorySize, SM_BYTES);

    dim3 grid(N_TOK / TOK);   // 256 blocks, 2 CTAs/SM
    dim3 block(TPB);
    router_kernel<<<grid, block, SM_BYTES>>>(x, gate, out, out_size);
}